// round 8
// baseline (speedup 1.0000x reference)
#include <cuda_runtime.h>
#include <cuda_bf16.h>
#include <cstdint>
#include <cstddef>

// ---------------------------------------------------------------------------
// Problem constants (fixed shapes: B=2, S=2048, E=2048, H=16, D=128)
// ---------------------------------------------------------------------------
#define BSZ   2
#define SEQ   2048
#define EMB   2048
#define NHEAD 16
#define HDIM  128
#define MROWS (BSZ * SEQ)      /* 4096 */
#define NQKV  (3 * EMB)        /* 6144 */

#define QK_SCALE 0.08838834764831845f  /* 128^-0.5 */

// ---------------------------------------------------------------------------
// Scratch (no cudaMalloc allowed -> __device__ globals)
// ---------------------------------------------------------------------------
__device__ float g_q[(size_t)BSZ * NHEAD * SEQ * HDIM];       // 33.6 MB
__device__ float g_k[(size_t)BSZ * NHEAD * SEQ * HDIM];
__device__ float g_v[(size_t)BSZ * NHEAD * SEQ * HDIM];
__device__ float g_att[(size_t)MROWS * EMB];                  // 33.6 MB

extern __shared__ unsigned char dyn_smem[];

__device__ __forceinline__ uint32_t smem_addr_u32(const void* p) {
    return (uint32_t)__cvta_generic_to_shared(p);
}
__device__ __forceinline__ uint32_t f2tf32(float f) {
    uint32_t r;
    asm("cvt.rna.tf32.f32 %0, %1;" : "=r"(r) : "f"(f));
    return r;
}
__device__ __forceinline__ void mma_tf32(float& d0, float& d1, float& d2, float& d3,
                                         uint32_t a0, uint32_t a1, uint32_t a2, uint32_t a3,
                                         uint32_t b0, uint32_t b1)
{
    asm volatile(
        "mma.sync.aligned.m16n8k8.row.col.f32.tf32.tf32.f32 "
        "{%0,%1,%2,%3}, {%4,%5,%6,%7}, {%8,%9}, {%0,%1,%2,%3};"
        : "+f"(d0), "+f"(d1), "+f"(d2), "+f"(d3)
        : "r"(a0), "r"(a1), "r"(a2), "r"(a3), "r"(b0), "r"(b1));
}
#define CP_ASYNC16(dst, src) \
    asm volatile("cp.async.ca.shared.global [%0], [%1], 16;\n" :: "r"(dst), "l"(src))
#define CP_COMMIT() asm volatile("cp.async.commit_group;\n")
#define CP_WAIT(n)  asm volatile("cp.async.wait_group %0;\n" :: "n"(n))

// ---------------------------------------------------------------------------
// TF32 tensor-core GEMM: CTA tile 128x256x32, 256 threads = 8 warps (2x4),
// warp tile 64x64.  A smem [m][k] pitch 36 with XOR swizzle (col ^= (row&3)<<3):
// conflict-free for STS.128 stores AND all a-frag LDS.  B smem [k][n] pitch 264.
// FUSE_ROPE: epilogue applies RoPE + scatters to g_q/g_k/g_v (QKV GEMM).
// ---------------------------------------------------------------------------
#define GBM 128
#define GBN 256
#define GBK 32
#define APITCH 36
#define BPITCH 264
#define GEMM_ABUF (GBM * APITCH)          /* 4608 u32 */
#define GEMM_BBUF (GBK * BPITCH)          /* 8448 u32 */
#define GEMM_BUF  (GEMM_ABUF + GEMM_BBUF) /* 13056 u32 */
#define GEMM_SMEM_BYTES (2 * GEMM_BUF * 4)   /* 104448 */

template <bool FUSE_ROPE>
__global__ __launch_bounds__(256)
void tf32_gemm_kernel(const float* __restrict__ A, const float* __restrict__ B,
                      float* __restrict__ C, const float* __restrict__ freqs,
                      int M, int N, int K)
{
    uint32_t* sm = (uint32_t*)dyn_smem;

    const int tid  = threadIdx.x;
    const int lane = tid & 31;
    const int w    = tid >> 5;         // 0..7
    const int wm   = (w >> 2) * 64;    // 0,64
    const int wn   = (w & 3) * 64;     // 0,64,128,192
    const int g    = lane >> 2;        // 0..7
    const int t4   = lane & 3;         // 0..3
    const int asw  = (g & 3) << 3;     // consumer-side A swizzle

    const int m0 = blockIdx.y * GBM;
    const int n0 = blockIdx.x * GBN;

    // loader assignments
    const int a_row = tid >> 3;            // 0..31 (+32*it, it<4)
    const int a_c4  = (tid & 7) << 2;      // 0..28
    const int a_sw  = a_c4 ^ ((a_row & 3) << 3);
    const int b_row = tid >> 6;            // 0..3  (+4*it, it<8)
    const int b_c4  = (tid & 63) << 2;     // 0..252

    const float* aP = A + (size_t)(m0 + a_row) * K + a_c4;
    const float* bP = B + (size_t)b_row * N + n0 + b_c4;

    float4 ra[4], rb[8];
    float d[4][8][4];
#pragma unroll
    for (int i = 0; i < 4; i++)
#pragma unroll
        for (int j = 0; j < 8; j++)
#pragma unroll
            for (int c = 0; c < 4; c++) d[i][j][c] = 0.f;

    const int nk = K / GBK;

#pragma unroll
    for (int it = 0; it < 4; ++it) ra[it] = *(const float4*)(aP + (size_t)(it * 32) * K);
#pragma unroll
    for (int it = 0; it < 8; ++it) rb[it] = *(const float4*)(bP + (size_t)(it * 4) * N);

    for (int tkt = 0; tkt < nk; ++tkt) {
        uint32_t* As = sm + (tkt & 1) * GEMM_BUF;
        uint32_t* Bs = As + GEMM_ABUF;

        // store current regs -> this buffer (cvt to tf32)
#pragma unroll
        for (int it = 0; it < 4; ++it) {
            uint4 va = make_uint4(f2tf32(ra[it].x), f2tf32(ra[it].y),
                                  f2tf32(ra[it].z), f2tf32(ra[it].w));
            *(uint4*)&As[(a_row + it * 32) * APITCH + a_sw] = va;
        }
#pragma unroll
        for (int it = 0; it < 8; ++it) {
            uint4 vb = make_uint4(f2tf32(rb[it].x), f2tf32(rb[it].y),
                                  f2tf32(rb[it].z), f2tf32(rb[it].w));
            *(uint4*)&Bs[(b_row + it * 4) * BPITCH + b_c4] = vb;
        }
        // prefetch next tile into registers
        if (tkt + 1 < nk) {
            const float* aN = aP + (size_t)(tkt + 1) * GBK;
            const float* bN = bP + (size_t)(tkt + 1) * GBK * N;
#pragma unroll
            for (int it = 0; it < 4; ++it) ra[it] = *(const float4*)(aN + (size_t)(it * 32) * K);
#pragma unroll
            for (int it = 0; it < 8; ++it) rb[it] = *(const float4*)(bN + (size_t)(it * 4) * N);
        }
        __syncthreads();

#pragma unroll
        for (int s = 0; s < 4; ++s) {
            const int kc = s * 8;
            uint32_t af[4][4], bf[8][2];
#pragma unroll
            for (int mf = 0; mf < 4; ++mf) {
                int r0 = wm + mf * 16 + g;
                int cs0 = (kc + t4) ^ asw;         // swizzled col (bit2 clear)
                af[mf][0] = As[r0 * APITCH + cs0];
                af[mf][1] = As[(r0 + 8) * APITCH + cs0];
                af[mf][2] = As[r0 * APITCH + cs0 + 4];
                af[mf][3] = As[(r0 + 8) * APITCH + cs0 + 4];
            }
#pragma unroll
            for (int nf = 0; nf < 8; ++nf) {
                int c0 = wn + nf * 8 + g;
                bf[nf][0] = Bs[(kc + t4) * BPITCH + c0];
                bf[nf][1] = Bs[(kc + t4 + 4) * BPITCH + c0];
            }
#pragma unroll
            for (int mf = 0; mf < 4; ++mf)
#pragma unroll
                for (int nf = 0; nf < 8; ++nf)
                    mma_tf32(d[mf][nf][0], d[mf][nf][1], d[mf][nf][2], d[mf][nf][3],
                             af[mf][0], af[mf][1], af[mf][2], af[mf][3],
                             bf[nf][0], bf[nf][1]);
        }
        __syncthreads();
    }

    if (!FUSE_ROPE) {
        // plain epilogue -> C
#pragma unroll
        for (int mf = 0; mf < 4; ++mf) {
#pragma unroll
            for (int nf = 0; nf < 8; ++nf) {
                int row = m0 + wm + mf * 16 + g;
                int col = n0 + wn + nf * 8 + 2 * t4;
                float* cp0 = C + (size_t)row * N + col;
                float* cp1 = C + (size_t)(row + 8) * N + col;
                *(float2*)cp0 = make_float2(d[mf][nf][0], d[mf][nf][1]);
                *(float2*)cp1 = make_float2(d[mf][nf][2], d[mf][nf][3]);
            }
        }
    } else {
        // fused RoPE + split epilogue.  mat uniform per CTA (GBN=256 divides 2048)
        const int mat = n0 >> 11;   // 0=q, 1=k, 2=v
        float* dst = (mat == 0) ? g_q : (mat == 1) ? g_k : g_v;
#pragma unroll
        for (int mf = 0; mf < 4; ++mf) {
            int row = m0 + wm + mf * 16 + g;
#pragma unroll
            for (int rr = 0; rr < 2; ++rr) {
                int r = row + rr * 8;
                int b = r >> 11;
                int s = r & 2047;
#pragma unroll
                for (int nf = 0; nf < 8; ++nf) {
                    int col = (n0 + wn + nf * 8 + 2 * t4) & 2047;  // within matrix
                    int h = col >> 7;
                    int dd = col & 127;                             // even
                    float vx = d[mf][nf][2 * rr + 0];
                    float vy = d[mf][nf][2 * rr + 1];
                    float2 o;
                    if (mat == 2) {
                        o = make_float2(vx, vy);
                    } else {
                        float2 cs = *(const float2*)&freqs[((size_t)s << 7) + dd];
                        float re = vx * cs.x - vy * cs.y;
                        float im = vy * cs.x + vx * cs.y;
                        if (mat == 0) { re *= QK_SCALE; im *= QK_SCALE; }
                        o = make_float2(re, im);
                    }
                    size_t off = (((size_t)(b * NHEAD + h) * SEQ + s) << 7) + dd;
                    *(float2*)&dst[off] = o;
                }
            }
        }
    }
}

// ---------------------------------------------------------------------------
// Flash attention (causal), tf32 tensor cores.  (verified R4/R5 kernel)
// BM=128 (8 warps x 16 rows), BN=64, D=128. Double-buffered cp.async K/V.
// ---------------------------------------------------------------------------
#define FKP 132
#define FVP 136
#define FBUF (64 * FKP + 64 * FVP)          /* 17152 floats */
#define FA_SMEM_BYTES (2 * FBUF * 4)        /* 137216 B */

__global__ __launch_bounds__(256, 1)
void flash_tc_kernel()
{
    float* fs = (float*)dyn_smem;

    const int tid  = threadIdx.x;
    const int lane = tid & 31;
    const int w    = tid >> 5;
    const int g    = lane >> 2;
    const int t4   = lane & 3;
    const int wm   = w * 16;

    const int qb = blockIdx.x;
    const int h  = blockIdx.y;
    const int b  = blockIdx.z;

    const size_t base = (size_t)(b * NHEAD + h) * SEQ * HDIM;
    const float* Qg = g_q + base + (size_t)qb * 128 * HDIM;
    const float* Kg = g_k + base;
    const float* Vg = g_v + base;

#pragma unroll
    for (int it = 0; it < 16; ++it) {
        int idx = tid + it * 256;
        int r  = idx >> 5;
        int c4 = (idx & 31) << 2;
        CP_ASYNC16(smem_addr_u32(&fs[r * FKP + c4]), Qg + (size_t)r * HDIM + c4);
    }
    CP_COMMIT();
    CP_WAIT(0);
    __syncthreads();

    uint32_t qa[16][4];
#pragma unroll
    for (int ks = 0; ks < 16; ++ks) {
        int kc = ks * 8;
        qa[ks][0] = f2tf32(fs[(wm + g) * FKP + kc + t4]);
        qa[ks][1] = f2tf32(fs[(wm + g + 8) * FKP + kc + t4]);
        qa[ks][2] = f2tf32(fs[(wm + g) * FKP + kc + t4 + 4]);
        qa[ks][3] = f2tf32(fs[(wm + g + 8) * FKP + kc + t4 + 4]);
    }
    __syncthreads();

    float m0 = -1e30f, m1 = -1e30f, l0 = 0.f, l1 = 0.f;
    float accO[16][4];
#pragma unroll
    for (int i = 0; i < 16; i++)
#pragma unroll
        for (int c = 0; c < 4; c++) accO[i][c] = 0.f;

    const int row0 = qb * 128 + wm + g;
    const int row1 = row0 + 8;
    const int nt   = 2 * qb + 2;

    const int kv_r  = tid >> 5;
    const int kv_c4 = (tid & 31) << 2;

#define FA_ISSUE(T, BUF)                                                      \
    do {                                                                      \
        float* kb_ = fs + (BUF) * FBUF;                                       \
        float* vb_ = kb_ + 64 * FKP;                                          \
        _Pragma("unroll")                                                     \
        for (int it_ = 0; it_ < 8; ++it_) {                                   \
            int r_ = kv_r + it_ * 8;                                          \
            size_t go_ = (size_t)((T) * 64 + r_) * HDIM + kv_c4;              \
            CP_ASYNC16(smem_addr_u32(&kb_[r_ * FKP + kv_c4]), Kg + go_);      \
            CP_ASYNC16(smem_addr_u32(&vb_[r_ * FVP + kv_c4]), Vg + go_);      \
        }                                                                     \
        CP_COMMIT();                                                          \
    } while (0)

    FA_ISSUE(0, 0);

    for (int t = 0; t < nt; ++t) {
        if (t + 1 < nt) { FA_ISSUE(t + 1, (t + 1) & 1); CP_WAIT(1); }
        else            { CP_WAIT(0); }
        __syncthreads();

        const float* Ks = fs + (t & 1) * FBUF;
        const float* Vs = Ks + 64 * FKP;
        const int colbase = t * 64;

        const bool dead = (colbase > qb * 128 + wm + 15);
        if (!dead) {
            float sc[8][4];
#pragma unroll
            for (int nf = 0; nf < 8; ++nf)
#pragma unroll
                for (int c = 0; c < 4; c++) sc[nf][c] = 0.f;

#pragma unroll
            for (int ks = 0; ks < 16; ++ks) {
                int kc = ks * 8;
#pragma unroll
                for (int nf = 0; nf < 8; ++nf) {
                    int c0 = nf * 8 + g;
                    uint32_t b0 = f2tf32(Ks[c0 * FKP + kc + t4]);
                    uint32_t b1 = f2tf32(Ks[c0 * FKP + kc + t4 + 4]);
                    mma_tf32(sc[nf][0], sc[nf][1], sc[nf][2], sc[nf][3],
                             qa[ks][0], qa[ks][1], qa[ks][2], qa[ks][3], b0, b1);
                }
            }

            if (colbase + 63 > row0) {
#pragma unroll
                for (int nf = 0; nf < 8; ++nf) {
                    int c = colbase + nf * 8 + 2 * t4;
                    if (c     > row0) sc[nf][0] = -1e30f;
                    if (c + 1 > row0) sc[nf][1] = -1e30f;
                    if (c     > row1) sc[nf][2] = -1e30f;
                    if (c + 1 > row1) sc[nf][3] = -1e30f;
                }
            }

            float mx0 = -1e30f, mx1 = -1e30f;
#pragma unroll
            for (int nf = 0; nf < 8; ++nf) {
                mx0 = fmaxf(mx0, fmaxf(sc[nf][0], sc[nf][1]));
                mx1 = fmaxf(mx1, fmaxf(sc[nf][2], sc[nf][3]));
            }
            mx0 = fmaxf(mx0, __shfl_xor_sync(0xffffffffu, mx0, 1));
            mx0 = fmaxf(mx0, __shfl_xor_sync(0xffffffffu, mx0, 2));
            mx1 = fmaxf(mx1, __shfl_xor_sync(0xffffffffu, mx1, 1));
            mx1 = fmaxf(mx1, __shfl_xor_sync(0xffffffffu, mx1, 2));

            float nm0 = fmaxf(m0, mx0), nm1 = fmaxf(m1, mx1);
            float s0 = __expf(m0 - nm0), s1 = __expf(m1 - nm1);
            float rs0 = 0.f, rs1 = 0.f;
#pragma unroll
            for (int nf = 0; nf < 8; ++nf) {
                sc[nf][0] = __expf(sc[nf][0] - nm0);
                sc[nf][1] = __expf(sc[nf][1] - nm0);
                sc[nf][2] = __expf(sc[nf][2] - nm1);
                sc[nf][3] = __expf(sc[nf][3] - nm1);
                rs0 += sc[nf][0] + sc[nf][1];
                rs1 += sc[nf][2] + sc[nf][3];
            }
            rs0 += __shfl_xor_sync(0xffffffffu, rs0, 1);
            rs0 += __shfl_xor_sync(0xffffffffu, rs0, 2);
            rs1 += __shfl_xor_sync(0xffffffffu, rs1, 1);
            rs1 += __shfl_xor_sync(0xffffffffu, rs1, 2);
            l0 = l0 * s0 + rs0;  m0 = nm0;
            l1 = l1 * s1 + rs1;  m1 = nm1;

#pragma unroll
            for (int nf = 0; nf < 16; ++nf) {
                accO[nf][0] *= s0; accO[nf][1] *= s0;
                accO[nf][2] *= s1; accO[nf][3] *= s1;
            }

            const int srcA = (lane & ~3) | (t4 >> 1);
            const int srcB = srcA + 2;
            const int e = t4 & 1;
#pragma unroll
            for (int ks = 0; ks < 8; ++ks) {
                float x0a = __shfl_sync(0xffffffffu, sc[ks][0], srcA);
                float x1a = __shfl_sync(0xffffffffu, sc[ks][1], srcA);
                float x2a = __shfl_sync(0xffffffffu, sc[ks][2], srcA);
                float x3a = __shfl_sync(0xffffffffu, sc[ks][3], srcA);
                float x0b = __shfl_sync(0xffffffffu, sc[ks][0], srcB);
                float x1b = __shfl_sync(0xffffffffu, sc[ks][1], srcB);
                float x2b = __shfl_sync(0xffffffffu, sc[ks][2], srcB);
                float x3b = __shfl_sync(0xffffffffu, sc[ks][3], srcB);
                uint32_t a0 = f2tf32(e ? x1a : x0a);
                uint32_t a1 = f2tf32(e ? x3a : x2a);
                uint32_t a2 = f2tf32(e ? x1b : x0b);
                uint32_t a3 = f2tf32(e ? x3b : x2b);
                const int vr0 = (ks * 8 + t4) * FVP;
                const int vr1 = (ks * 8 + t4 + 4) * FVP;
#pragma unroll
                for (int nf = 0; nf < 16; ++nf) {
                    uint32_t b0 = f2tf32(Vs[vr0 + nf * 8 + g]);
                    uint32_t b1 = f2tf32(Vs[vr1 + nf * 8 + g]);
                    mma_tf32(accO[nf][0], accO[nf][1], accO[nf][2], accO[nf][3],
                             a0, a1, a2, a3, b0, b1);
                }
            }
        }
        __syncthreads();
    }

    float i0 = 1.f / l0, i1 = 1.f / l1;
    float* o0 = g_att + ((size_t)b * SEQ + row0) * EMB + h * HDIM;
    float* o1 = g_att + ((size_t)b * SEQ + row1) * EMB + h * HDIM;
#pragma unroll
    for (int nf = 0; nf < 16; ++nf) {
        int col = nf * 8 + 2 * t4;
        *(float2*)&o0[col] = make_float2(accO[nf][0] * i0, accO[nf][1] * i0);
        *(float2*)&o1[col] = make_float2(accO[nf][2] * i1, accO[nf][3] * i1);
    }
}

// ---------------------------------------------------------------------------
// Launcher
// ---------------------------------------------------------------------------
extern "C" void kernel_launch(void* const* d_in, const int* in_sizes, int n_in,
                              void* d_out, int out_size)
{
    const float* x     = (const float*)d_in[0];
    const float* Wqkv  = (const float*)d_in[1];
    const float* Wo    = (const float*)d_in[2];
    const float* freqs = (const float*)d_in[3];
    float* out = (float*)d_out;

    float* p_att = nullptr;
    cudaGetSymbolAddress((void**)&p_att, g_att);

    cudaFuncSetAttribute(tf32_gemm_kernel<true>,
                         cudaFuncAttributeMaxDynamicSharedMemorySize,
                         GEMM_SMEM_BYTES);
    cudaFuncSetAttribute(tf32_gemm_kernel<false>,
                         cudaFuncAttributeMaxDynamicSharedMemorySize,
                         GEMM_SMEM_BYTES);
    cudaFuncSetAttribute(flash_tc_kernel,
                         cudaFuncAttributeMaxDynamicSharedMemorySize,
                         FA_SMEM_BYTES);

    // 1) qkv = x @ Wqkv with fused RoPE + split into g_q/g_k/g_v
    {
        dim3 grid(NQKV / GBN, MROWS / GBM);  // 24 x 32
        tf32_gemm_kernel<true><<<grid, 256, GEMM_SMEM_BYTES>>>(
            x, Wqkv, nullptr, freqs, MROWS, NQKV, EMB);
    }
    // 2) causal flash attention (tf32 tensor cores)
    {
        dim3 grid(SEQ / 128, NHEAD, BSZ);    // 16 x 16 x 2
        flash_tc_kernel<<<grid, 256, FA_SMEM_BYTES>>>();
    }
    // 3) out = att @ Wo
    {
        dim3 grid(EMB / GBN, MROWS / GBM);   // 8 x 32
        tf32_gemm_kernel<false><<<grid, 256, GEMM_SMEM_BYTES>>>(
            p_att, Wo, out, nullptr, MROWS, EMB, EMB);
    }
}